// round 1
// baseline (speedup 1.0000x reference)
#include <cuda_runtime.h>
#include <cstdint>

#define D_IN  128
#define D_HID 128
#define D_OUT 64
#define MAXN  100000

// ---- scratch (static __device__ arrays; no allocation allowed) ----
__device__ float g_h1s[MAXN * D_HID];   // scaled layer-1 features (gather source)
__device__ float g_agg1[MAXN * D_HID];  // layer-1 accumulator
__device__ float g_h1[MAXN * D_HID];    // relu(layer-1 out)
__device__ float g_h2s[MAXN * D_OUT];   // scaled layer-2 features
__device__ float g_agg2[MAXN * D_OUT];  // layer-2 accumulator
__device__ float g_dinv[MAXN];
__device__ int   g_deg[MAXN];

// ---------------- degree / normalization ----------------
__global__ void zero_deg_kernel(int n) {
    int i = blockIdx.x * blockDim.x + threadIdx.x;
    if (i < n) g_deg[i] = 0;
}

__global__ void deg_kernel(const int* __restrict__ dst, int E) {
    int e = blockIdx.x * blockDim.x + threadIdx.x;
    if (e < E) atomicAdd(&g_deg[dst[e]], 1);
}

__global__ void dinv_kernel(int n) {
    int i = blockIdx.x * blockDim.x + threadIdx.x;
    if (i < n) g_dinv[i] = rsqrtf((float)(g_deg[i] + 1));  // +1 self-loop
}

// ---------------- fused GEMM + dinv scale, dual-store ----------------
// C = (A[M,K] @ B[K,BN]) * dinv[row] -> out1 and out2 (accumulator init)
template <int BM, int BN, int BK, int TM, int TN>
__global__ void __launch_bounds__(256)
gemm_scale_kernel(const float* __restrict__ A, const float* __restrict__ B,
                  const float* __restrict__ dinv,
                  float* __restrict__ out1, float* __restrict__ out2,
                  int M, int K)
{
    constexpr int NT = (BM / TM) * (BN / TN);   // = 256
    __shared__ float As[BK][BM];
    __shared__ float Bs[BK][BN];

    const int tid = threadIdx.x;
    const int bm  = blockIdx.x * BM;

    const int tcol = tid % (BN / TN);
    const int trow = tid / (BN / TN);

    // A tile load mapping (float4)
    const int aRow = tid / (BK / 4);
    const int aCol = (tid % (BK / 4)) * 4;
    // B tile load mapping (float4)
    const int bRow = tid / (BN / 4);
    const int bCol = (tid % (BN / 4)) * 4;

    float acc[TM][TN] = {};
    float regM[TM], regN[TN];

    for (int k0 = 0; k0 < K; k0 += BK) {
        {   // stage A (transposed in smem)
            int gr = bm + aRow;
            float4 v = make_float4(0.f, 0.f, 0.f, 0.f);
            if (gr < M)
                v = *reinterpret_cast<const float4*>(&A[(size_t)gr * K + k0 + aCol]);
            As[aCol + 0][aRow] = v.x;
            As[aCol + 1][aRow] = v.y;
            As[aCol + 2][aRow] = v.z;
            As[aCol + 3][aRow] = v.w;
        }
        {   // stage B
            if (BK * BN / 4 == NT || tid < BK * BN / 4) {
                float4 v = *reinterpret_cast<const float4*>(
                    &B[(size_t)(k0 + bRow) * BN + bCol]);
                *reinterpret_cast<float4*>(&Bs[bRow][bCol]) = v;
            }
        }
        __syncthreads();

        #pragma unroll
        for (int k = 0; k < BK; k++) {
            #pragma unroll
            for (int i = 0; i < TM; i += 4) {
                float4 v = *reinterpret_cast<const float4*>(&As[k][trow * TM + i]);
                regM[i+0] = v.x; regM[i+1] = v.y; regM[i+2] = v.z; regM[i+3] = v.w;
            }
            #pragma unroll
            for (int j = 0; j < TN; j += 4) {
                float4 v = *reinterpret_cast<const float4*>(&Bs[k][tcol * TN + j]);
                regN[j+0] = v.x; regN[j+1] = v.y; regN[j+2] = v.z; regN[j+3] = v.w;
            }
            #pragma unroll
            for (int i = 0; i < TM; i++)
                #pragma unroll
                for (int j = 0; j < TN; j++)
                    acc[i][j] += regM[i] * regN[j];
        }
        __syncthreads();
    }

    #pragma unroll
    for (int i = 0; i < TM; i++) {
        int gr = bm + trow * TM + i;
        if (gr >= M) continue;
        float s = dinv[gr];
        #pragma unroll
        for (int j = 0; j < TN; j += 4) {
            float4 v;
            v.x = acc[i][j+0] * s;
            v.y = acc[i][j+1] * s;
            v.z = acc[i][j+2] * s;
            v.w = acc[i][j+3] * s;
            size_t off = (size_t)gr * BN + tcol * TN + j;
            *reinterpret_cast<float4*>(&out1[off]) = v;
            *reinterpret_cast<float4*>(&out2[off]) = v;
        }
    }
}

// ---------------- edge scatter: agg[dst] += hs[src] ----------------
__device__ __forceinline__ void red_add_v4(float* p, float4 v) {
    size_t gp = __cvta_generic_to_global(p);
    asm volatile("red.global.add.v4.f32 [%0], {%1, %2, %3, %4};"
                 :: "l"(gp), "f"(v.x), "f"(v.y), "f"(v.z), "f"(v.w)
                 : "memory");
}

template <int NCOL>
__global__ void scatter_kernel(const float* __restrict__ hs,
                               const int* __restrict__ src,
                               const int* __restrict__ dst,
                               float* __restrict__ agg, int E)
{
    constexpr int G = NCOL / 4;                 // float4 groups per edge
    int i = blockIdx.x * blockDim.x + threadIdx.x;
    int total = E * G;
    if (i >= total) return;
    int e = i / G;
    int g = i % G;
    int s = __ldg(&src[e]);
    int d = __ldg(&dst[e]);
    float4 v = *reinterpret_cast<const float4*>(&hs[(size_t)s * NCOL + g * 4]);
    red_add_v4(&agg[(size_t)d * NCOL + g * 4], v);
}

// ---------------- elementwise epilogues ----------------
__global__ void relu_bias_kernel(const float* __restrict__ agg,
                                 const float* __restrict__ b,
                                 const float* __restrict__ dinv,
                                 float* __restrict__ out, int M)
{
    constexpr int G = D_HID / 4;
    int i = blockIdx.x * blockDim.x + threadIdx.x;
    int total = M * G;
    if (i >= total) return;
    int row = i / G;
    int c4  = i % G;
    float s = dinv[row];
    float4 a  = *reinterpret_cast<const float4*>(&agg[(size_t)i * 4]);
    float4 bb = *reinterpret_cast<const float4*>(&b[c4 * 4]);
    float4 r;
    r.x = fmaxf(a.x * s + bb.x, 0.f);
    r.y = fmaxf(a.y * s + bb.y, 0.f);
    r.z = fmaxf(a.z * s + bb.z, 0.f);
    r.w = fmaxf(a.w * s + bb.w, 0.f);
    *reinterpret_cast<float4*>(&out[(size_t)i * 4]) = r;
}

__global__ void final_bias_kernel(const float* __restrict__ agg,
                                  const float* __restrict__ b,
                                  const float* __restrict__ dinv,
                                  float* __restrict__ out, int M)
{
    constexpr int G = D_OUT / 4;
    int i = blockIdx.x * blockDim.x + threadIdx.x;
    int total = M * G;
    if (i >= total) return;
    int row = i / G;
    int c4  = i % G;
    float s = dinv[row];
    float4 a  = *reinterpret_cast<const float4*>(&agg[(size_t)i * 4]);
    float4 bb = *reinterpret_cast<const float4*>(&b[c4 * 4]);
    float4 r;
    r.x = a.x * s + bb.x;
    r.y = a.y * s + bb.y;
    r.z = a.z * s + bb.z;
    r.w = a.w * s + bb.w;
    *reinterpret_cast<float4*>(&out[(size_t)i * 4]) = r;
}

// ---------------- launch ----------------
extern "C" void kernel_launch(void* const* d_in, const int* in_sizes, int n_in,
                              void* d_out, int out_size)
{
    const float* x  = (const float*)d_in[0];
    const int*   ei = (const int*)  d_in[1];
    const float* W1 = (const float*)d_in[2];
    const float* b1 = (const float*)d_in[3];
    const float* W2 = (const float*)d_in[4];
    const float* b2 = (const float*)d_in[5];
    float* out = (float*)d_out;

    const int M = in_sizes[0] / D_IN;      // 100000
    const int E = in_sizes[1] / 2;         // 1600000
    const int* src = ei;
    const int* dst = ei + E;

    float *p_h1s, *p_agg1, *p_h1, *p_h2s, *p_agg2, *p_dinv;
    cudaGetSymbolAddress((void**)&p_h1s,  g_h1s);
    cudaGetSymbolAddress((void**)&p_agg1, g_agg1);
    cudaGetSymbolAddress((void**)&p_h1,   g_h1);
    cudaGetSymbolAddress((void**)&p_h2s,  g_h2s);
    cudaGetSymbolAddress((void**)&p_agg2, g_agg2);
    cudaGetSymbolAddress((void**)&p_dinv, g_dinv);

    const int T = 256;

    // 1. symmetric-normalization degrees
    zero_deg_kernel<<<(M + T - 1) / T, T>>>(M);
    deg_kernel<<<(E + T - 1) / T, T>>>(dst, E);
    dinv_kernel<<<(M + T - 1) / T, T>>>(M);

    // 2. layer 1: h1s = (x @ W1) * dinv ; agg1 = h1s (self-loop init)
    gemm_scale_kernel<128, 128, 8, 8, 8>
        <<<(M + 127) / 128, 256>>>(x, W1, p_dinv, p_h1s, p_agg1, M, D_IN);

    // 3. agg1[dst] += h1s[src] over real edges
    {
        int total = E * (D_HID / 4);
        scatter_kernel<D_HID><<<(total + T - 1) / T, T>>>(p_h1s, src, dst, p_agg1, E);
    }

    // 4. h1 = relu(agg1 * dinv + b1)
    {
        int total = M * (D_HID / 4);
        relu_bias_kernel<<<(total + T - 1) / T, T>>>(p_agg1, b1, p_dinv, p_h1, M);
    }

    // 5. layer 2: h2s = (h1 @ W2) * dinv ; agg2 = h2s
    gemm_scale_kernel<128, 64, 8, 8, 4>
        <<<(M + 127) / 128, 256>>>(p_h1, W2, p_dinv, p_h2s, p_agg2, M, D_HID);

    // 6. agg2[dst] += h2s[src]
    {
        int total = E * (D_OUT / 4);
        scatter_kernel<D_OUT><<<(total + T - 1) / T, T>>>(p_h2s, src, dst, p_agg2, E);
    }

    // 7. out = agg2 * dinv + b2
    {
        int total = M * (D_OUT / 4);
        final_bias_kernel<<<(total + T - 1) / T, T>>>(p_agg2, b2, p_dinv, out, M);
    }
}

// round 3
// speedup vs baseline: 1.2293x; 1.2293x over previous
#include <cuda_runtime.h>
#include <cstdint>

#define D_IN  128
#define D_HID 128
#define D_OUT 64
#define MAXN  100000

// ---- scratch ----
__device__ float g_h1s[MAXN * D_HID];
__device__ float g_agg1[MAXN * D_HID];
__device__ float g_h2s[MAXN * D_OUT];
__device__ float g_agg2[MAXN * D_OUT];
__device__ float g_dinv[MAXN];
__device__ int   g_deg[MAXN];
__device__ float g_Wt1[D_HID * D_IN];   // [N=128][K=128] K-major (W1^T)
__device__ float g_Wt2[D_OUT * D_HID];  // [N=64][K=128]  K-major (W2^T)

// ================= degree / normalization =================
__global__ void zero_deg_kernel(int n) {
    int i = blockIdx.x * blockDim.x + threadIdx.x;
    if (i < n) g_deg[i] = 0;
}
__global__ void deg_kernel(const int* __restrict__ dst, int E) {
    int e = blockIdx.x * blockDim.x + threadIdx.x;
    if (e < E) atomicAdd(&g_deg[dst[e]], 1);
}
__global__ void dinv_kernel(int n) {
    int i = blockIdx.x * blockDim.x + threadIdx.x;
    if (i < n) g_dinv[i] = rsqrtf((float)(g_deg[i] + 1));
}

// ================= weight transpose =================
__global__ void transpose_w_kernel(const float* __restrict__ W1,
                                   const float* __restrict__ W2) {
    int i = blockIdx.x * blockDim.x + threadIdx.x;
    if (i < D_IN * D_HID) {
        int k = i / D_HID, n = i % D_HID;
        g_Wt1[n * D_IN + k] = W1[k * D_HID + n];
    }
    if (i < D_HID * D_OUT) {
        int k = i / D_OUT, n = i % D_OUT;
        g_Wt2[n * D_HID + k] = W2[k * D_OUT + n];
    }
}

// ================= tf32 helpers =================
__device__ __forceinline__ uint32_t f2tf32(float f) {
    uint32_t u;
    asm("cvt.rna.tf32.f32 %0, %1;" : "=r"(u) : "f"(f));
    return u;
}
__device__ __forceinline__ void mma_tf32(float* c, const uint32_t* a,
                                         const uint32_t* b) {
    asm volatile(
        "mma.sync.aligned.m16n8k8.row.col.f32.tf32.tf32.f32 "
        "{%0,%1,%2,%3}, {%4,%5,%6,%7}, {%8,%9}, {%0,%1,%2,%3};"
        : "+f"(c[0]), "+f"(c[1]), "+f"(c[2]), "+f"(c[3])
        : "r"(a[0]), "r"(a[1]), "r"(a[2]), "r"(a[3]), "r"(b[0]), "r"(b[1]));
}

// ================ mma.sync tf32 GEMM: out = (A @ Bt^T) * dinv, dual-store
// A: [M,128] row-major (optional fused relu(a*dinv+bias) on load)
// Bt: [N,128] K-major.  out1/out2: [M,N]
// Block: 128 rows x N cols, 256 threads (8 warps: 4 along M, 2 along N).
template <int N, bool RELU>
__global__ void __launch_bounds__(256)
mma_gcn_kernel(const float* __restrict__ A, const float* __restrict__ Bt,
               const float* __restrict__ dinv, const float* __restrict__ bias,
               float* __restrict__ out1, float* __restrict__ out2, int M)
{
    constexpr int K  = 128;
    constexpr int P  = 132;          // smem pitch (floats): conflict-free frags
    constexpr int WN = N / 2;        // warp N-tile
    constexpr int NT = WN / 8;       // n8 frags per warp
    extern __shared__ uint32_t smem[];
    uint32_t* As = smem;             // 128 x P
    uint32_t* Bs = smem + 128 * P;   // N x P

    const int tid    = threadIdx.x;
    const int warp   = tid >> 5;
    const int lane   = tid & 31;
    const int warp_m = warp & 3;
    const int warp_n = warp >> 2;
    const int bm     = blockIdx.x * 128;

    // ---- stage A (128 x 128), fused transform, tf32 round ----
    #pragma unroll
    for (int it = 0; it < 16; it++) {
        int idx = tid + it * 256;            // 4096 float4 groups
        int row = idx >> 5;
        int g   = idx & 31;
        int grow = bm + row;
        float4 v = make_float4(0.f, 0.f, 0.f, 0.f);
        if (grow < M) {
            v = *reinterpret_cast<const float4*>(&A[(size_t)grow * K + g * 4]);
            if (RELU) {
                float s = dinv[grow];
                float4 bb = *reinterpret_cast<const float4*>(&bias[g * 4]);
                v.x = fmaxf(fmaf(v.x, s, bb.x), 0.f);
                v.y = fmaxf(fmaf(v.y, s, bb.y), 0.f);
                v.z = fmaxf(fmaf(v.z, s, bb.z), 0.f);
                v.w = fmaxf(fmaf(v.w, s, bb.w), 0.f);
            }
        }
        uint4 u = make_uint4(f2tf32(v.x), f2tf32(v.y), f2tf32(v.z), f2tf32(v.w));
        *reinterpret_cast<uint4*>(&As[row * P + g * 4]) = u;
    }
    // ---- stage B (N x 128) ----
    #pragma unroll
    for (int it = 0; it < N / 8; it++) {
        int idx = tid + it * 256;            // N*32 float4 groups
        int row = idx >> 5;
        int g   = idx & 31;
        float4 v = *reinterpret_cast<const float4*>(&Bt[(size_t)row * K + g * 4]);
        uint4 u = make_uint4(f2tf32(v.x), f2tf32(v.y), f2tf32(v.z), f2tf32(v.w));
        *reinterpret_cast<uint4*>(&Bs[row * P + g * 4]) = u;
    }
    __syncthreads();

    // ---- mainloop: 16 k-steps of k8 ----
    float c[2][NT][4];
    #pragma unroll
    for (int mt = 0; mt < 2; mt++)
        #pragma unroll
        for (int nt = 0; nt < NT; nt++)
            #pragma unroll
            for (int j = 0; j < 4; j++) c[mt][nt][j] = 0.f;

    const int lq = lane >> 2;        // lane / 4
    const int lr = lane & 3;         // lane % 4

    #pragma unroll
    for (int ks = 0; ks < 16; ks++) {
        const int k0 = ks * 8 + lr;
        uint32_t a[2][4];
        #pragma unroll
        for (int mt = 0; mt < 2; mt++) {
            int r = warp_m * 32 + mt * 16 + lq;
            a[mt][0] = As[r * P + k0];
            a[mt][1] = As[(r + 8) * P + k0];
            a[mt][2] = As[r * P + k0 + 4];
            a[mt][3] = As[(r + 8) * P + k0 + 4];
        }
        uint32_t b[NT][2];
        #pragma unroll
        for (int nt = 0; nt < NT; nt++) {
            int n = warp_n * WN + nt * 8 + lq;
            b[nt][0] = Bs[n * P + k0];
            b[nt][1] = Bs[n * P + k0 + 4];
        }
        #pragma unroll
        for (int mt = 0; mt < 2; mt++)
            #pragma unroll
            for (int nt = 0; nt < NT; nt++)
                mma_tf32(c[mt][nt], a[mt], b[nt]);
    }

    // ---- epilogue: dinv scale + dual store ----
    #pragma unroll
    for (int mt = 0; mt < 2; mt++) {
        int r0 = bm + warp_m * 32 + mt * 16 + lq;
        int r1 = r0 + 8;
        float s0 = (r0 < M) ? dinv[r0] : 0.f;
        float s1 = (r1 < M) ? dinv[r1] : 0.f;
        #pragma unroll
        for (int nt = 0; nt < NT; nt++) {
            int n = warp_n * WN + nt * 8 + 2 * lr;
            if (r0 < M) {
                float2 v = make_float2(c[mt][nt][0] * s0, c[mt][nt][1] * s0);
                size_t off = (size_t)r0 * N + n;
                *reinterpret_cast<float2*>(&out1[off]) = v;
                *reinterpret_cast<float2*>(&out2[off]) = v;
            }
            if (r1 < M) {
                float2 v = make_float2(c[mt][nt][2] * s1, c[mt][nt][3] * s1);
                size_t off = (size_t)r1 * N + n;
                *reinterpret_cast<float2*>(&out1[off]) = v;
                *reinterpret_cast<float2*>(&out2[off]) = v;
            }
        }
    }
}

// ================= edge scatter =================
__device__ __forceinline__ void red_add_v4(float* p, float4 v) {
    size_t gp = __cvta_generic_to_global(p);
    asm volatile("red.global.add.v4.f32 [%0], {%1, %2, %3, %4};"
                 :: "l"(gp), "f"(v.x), "f"(v.y), "f"(v.z), "f"(v.w)
                 : "memory");
}

template <int NCOL>
__global__ void scatter_kernel(const float* __restrict__ hs,
                               const int* __restrict__ src,
                               const int* __restrict__ dst,
                               float* __restrict__ agg, int E)
{
    constexpr int G = NCOL / 4;
    int i = blockIdx.x * blockDim.x + threadIdx.x;
    int total = E * G;
    if (i >= total) return;
    int e = i / G;
    int g = i % G;
    int s = __ldg(&src[e]);
    int d = __ldg(&dst[e]);
    float4 v = *reinterpret_cast<const float4*>(&hs[(size_t)s * NCOL + g * 4]);
    red_add_v4(&agg[(size_t)d * NCOL + g * 4], v);
}

// ================= final epilogue =================
__global__ void final_bias_kernel(const float* __restrict__ agg,
                                  const float* __restrict__ b,
                                  const float* __restrict__ dinv,
                                  float* __restrict__ out, int M)
{
    constexpr int G = D_OUT / 4;
    int i = blockIdx.x * blockDim.x + threadIdx.x;
    int total = M * G;
    if (i >= total) return;
    int row = i / G;
    int c4  = i % G;
    float s = dinv[row];
    float4 a  = *reinterpret_cast<const float4*>(&agg[(size_t)i * 4]);
    float4 bb = *reinterpret_cast<const float4*>(&b[c4 * 4]);
    float4 r;
    r.x = fmaf(a.x, s, bb.x);
    r.y = fmaf(a.y, s, bb.y);
    r.z = fmaf(a.z, s, bb.z);
    r.w = fmaf(a.w, s, bb.w);
    *reinterpret_cast<float4*>(&out[(size_t)i * 4]) = r;
}

// ================= launch =================
extern "C" void kernel_launch(void* const* d_in, const int* in_sizes, int n_in,
                              void* d_out, int out_size)
{
    const float* x  = (const float*)d_in[0];
    const int*   ei = (const int*)  d_in[1];
    const float* W1 = (const float*)d_in[2];
    const float* b1 = (const float*)d_in[3];
    const float* W2 = (const float*)d_in[4];
    const float* b2 = (const float*)d_in[5];
    float* out = (float*)d_out;

    const int M = in_sizes[0] / D_IN;
    const int E = in_sizes[1] / 2;
    const int* src = ei;
    const int* dst = ei + E;

    float *p_h1s, *p_agg1, *p_h2s, *p_agg2, *p_dinv, *p_Wt1, *p_Wt2;
    cudaGetSymbolAddress((void**)&p_h1s,  g_h1s);
    cudaGetSymbolAddress((void**)&p_agg1, g_agg1);
    cudaGetSymbolAddress((void**)&p_h2s,  g_h2s);
    cudaGetSymbolAddress((void**)&p_agg2, g_agg2);
    cudaGetSymbolAddress((void**)&p_dinv, g_dinv);
    cudaGetSymbolAddress((void**)&p_Wt1,  g_Wt1);
    cudaGetSymbolAddress((void**)&p_Wt2,  g_Wt2);

    const int T = 256;
    const int smem1 = (128 + 128) * 132 * 4;   // 135168 B
    const int smem2 = (128 + 64) * 132 * 4;    // 101376 B
    cudaFuncSetAttribute(mma_gcn_kernel<128, false>,
                         cudaFuncAttributeMaxDynamicSharedMemorySize, smem1);
    cudaFuncSetAttribute(mma_gcn_kernel<64, true>,
                         cudaFuncAttributeMaxDynamicSharedMemorySize, smem2);

    // 1. degrees + weight transpose
    zero_deg_kernel<<<(M + T - 1) / T, T>>>(M);
    deg_kernel<<<(E + T - 1) / T, T>>>(dst, E);
    dinv_kernel<<<(M + T - 1) / T, T>>>(M);
    transpose_w_kernel<<<(D_IN * D_HID + T - 1) / T, T>>>(W1, W2);

    const int nblk = (M + 127) / 128;

    // 2. layer 1 GEMM (mma.sync tf32): h1s = agg1 = (x@W1)*dinv
    mma_gcn_kernel<128, false><<<nblk, 256, smem1>>>(
        x, p_Wt1, p_dinv, nullptr, p_h1s, p_agg1, M);

    // 3. agg1[dst] += h1s[src]
    {
        int total = E * (D_HID / 4);
        scatter_kernel<D_HID><<<(total + T - 1) / T, T>>>(p_h1s, src, dst, p_agg1, E);
    }

    // 4+5. layer 2 GEMM with fused relu(agg1*dinv+b1) on A-load
    mma_gcn_kernel<64, true><<<nblk, 256, smem2>>>(
        p_agg1, p_Wt2, p_dinv, b1, p_h2s, p_agg2, M);

    // 6. agg2[dst] += h2s[src]
    {
        int total = E * (D_OUT / 4);
        scatter_kernel<D_OUT><<<(total + T - 1) / T, T>>>(p_h2s, src, dst, p_agg2, E);
    }

    // 7. out = agg2*dinv + b2
    {
        int total = M * (D_OUT / 4);
        final_bias_kernel<<<(total + T - 1) / T, T>>>(p_agg2, b2, p_dinv, out, M);
    }
}

// round 4
// speedup vs baseline: 2.3345x; 1.8990x over previous
#include <cuda_runtime.h>
#include <cstdint>

#define D_IN  128
#define D_HID 128
#define D_OUT 64
#define MAXN  100000
#define MAXE  1600000
#define SCAN_TILE 1024
#define MAX_TILES ((MAXN + SCAN_TILE - 1) / SCAN_TILE)   // 98

// ---- scratch ----
__device__ float g_h1s[MAXN * D_HID];   // (x@W1)*dinv
__device__ float g_agg1[MAXN * D_HID];  // pull-aggregated layer-1
__device__ float g_h2s[MAXN * D_OUT];   // (h1@W2)*dinv
__device__ float g_dinv[MAXN];
__device__ int   g_deg[MAXN];
__device__ int   g_rowptr[MAXN];
__device__ int   g_cursor[MAXN];
__device__ int   g_tilesum[MAX_TILES];
__device__ int   g_csrsrc[MAXE];
__device__ float g_Wt1[D_HID * D_IN];   // [N=128][K=128] K-major (W1^T)
__device__ float g_Wt2[D_OUT * D_HID];  // [N=64][K=128]  K-major (W2^T)

// ================= degree / normalization =================
__global__ void zero_deg_kernel(int n) {
    int i = blockIdx.x * blockDim.x + threadIdx.x;
    if (i < n) g_deg[i] = 0;
}
__global__ void deg_kernel(const int* __restrict__ dst, int E) {
    int e = blockIdx.x * blockDim.x + threadIdx.x;
    if (e < E) atomicAdd(&g_deg[dst[e]], 1);
}
__global__ void dinv_kernel(int n) {
    int i = blockIdx.x * blockDim.x + threadIdx.x;
    if (i < n) g_dinv[i] = rsqrtf((float)(g_deg[i] + 1));
}

// ================= CSR build: exclusive scan of deg =================
// scan1: per-tile (1024 elems, 256 threads x 4) exclusive scan + tile totals
__global__ void __launch_bounds__(256) scan1_kernel(int n) {
    __shared__ int wsum[8];
    const int tid  = threadIdx.x;
    const int lane = tid & 31, wid = tid >> 5;
    const int base = blockIdx.x * SCAN_TILE + tid * 4;

    int v0 = 0, v1 = 0, v2 = 0, v3 = 0;
    if (base + 0 < n) v0 = g_deg[base + 0];
    if (base + 1 < n) v1 = g_deg[base + 1];
    if (base + 2 < n) v2 = g_deg[base + 2];
    if (base + 3 < n) v3 = g_deg[base + 3];
    int tsum = v0 + v1 + v2 + v3;

    int x = tsum;
    #pragma unroll
    for (int o = 1; o < 32; o <<= 1) {
        int y = __shfl_up_sync(0xFFFFFFFFu, x, o);
        if (lane >= o) x += y;
    }
    if (lane == 31) wsum[wid] = x;
    __syncthreads();
    if (wid == 0 && lane < 8) {
        int w = wsum[lane];
        #pragma unroll
        for (int o = 1; o < 8; o <<= 1) {
            int y = __shfl_up_sync(0xFFu, w, o);
            if (lane >= o) w += y;
        }
        wsum[lane] = w;
    }
    __syncthreads();
    int warp_off = (wid == 0) ? 0 : wsum[wid - 1];
    int excl = warp_off + x - tsum;          // exclusive prefix of this thread

    if (base + 0 < n) g_rowptr[base + 0] = excl;
    if (base + 1 < n) g_rowptr[base + 1] = excl + v0;
    if (base + 2 < n) g_rowptr[base + 2] = excl + v0 + v1;
    if (base + 3 < n) g_rowptr[base + 3] = excl + v0 + v1 + v2;
    if (tid == 0) g_tilesum[blockIdx.x] = 0;     // placeholder; set below
    __syncthreads();
    if (tid == 255) g_tilesum[blockIdx.x] = warp_off + x;  // block total
}

// scan2: single block exclusive scan over tile totals
__global__ void __launch_bounds__(128) scan2_kernel(int ntiles) {
    __shared__ int wsum[4];
    const int tid = threadIdx.x;
    const int lane = tid & 31, wid = tid >> 5;
    int v = (tid < ntiles) ? g_tilesum[tid] : 0;
    int x = v;
    #pragma unroll
    for (int o = 1; o < 32; o <<= 1) {
        int y = __shfl_up_sync(0xFFFFFFFFu, x, o);
        if (lane >= o) x += y;
    }
    if (lane == 31) wsum[wid] = x;
    __syncthreads();
    if (wid == 0 && lane < 4) {
        int w = wsum[lane];
        #pragma unroll
        for (int o = 1; o < 4; o <<= 1) {
            int y = __shfl_up_sync(0xFu, w, o);
            if (lane >= o) w += y;
        }
        wsum[lane] = w;
    }
    __syncthreads();
    int warp_off = (wid == 0) ? 0 : wsum[wid - 1];
    if (tid < ntiles) g_tilesum[tid] = warp_off + x - v;   // exclusive
}

// scan3: add tile offsets; init cursor
__global__ void scan3_kernel(int n) {
    int i = blockIdx.x * blockDim.x + threadIdx.x;
    if (i < n) {
        int r = g_rowptr[i] + g_tilesum[i >> 10];
        g_rowptr[i] = r;
        g_cursor[i] = r;
    }
}

__global__ void fill_kernel(const int* __restrict__ src,
                            const int* __restrict__ dst, int E) {
    int e = blockIdx.x * blockDim.x + threadIdx.x;
    if (e < E) {
        int pos = atomicAdd(&g_cursor[dst[e]], 1);
        g_csrsrc[pos] = src[e];
    }
}

// ================= weight transpose =================
__global__ void transpose_w_kernel(const float* __restrict__ W1,
                                   const float* __restrict__ W2) {
    int i = blockIdx.x * blockDim.x + threadIdx.x;
    if (i < D_IN * D_HID) {
        int k = i / D_HID, n = i % D_HID;
        g_Wt1[n * D_IN + k] = W1[k * D_HID + n];
    }
    if (i < D_HID * D_OUT) {
        int k = i / D_OUT, n = i % D_OUT;
        g_Wt2[n * D_HID + k] = W2[k * D_OUT + n];
    }
}

// ================= tf32 helpers =================
__device__ __forceinline__ uint32_t f2tf32(float f) {
    uint32_t u;
    asm("cvt.rna.tf32.f32 %0, %1;" : "=r"(u) : "f"(f));
    return u;
}
__device__ __forceinline__ void mma_tf32(float* c, const uint32_t* a,
                                         const uint32_t* b) {
    asm volatile(
        "mma.sync.aligned.m16n8k8.row.col.f32.tf32.tf32.f32 "
        "{%0,%1,%2,%3}, {%4,%5,%6,%7}, {%8,%9}, {%0,%1,%2,%3};"
        : "+f"(c[0]), "+f"(c[1]), "+f"(c[2]), "+f"(c[3])
        : "r"(a[0]), "r"(a[1]), "r"(a[2]), "r"(a[3]), "r"(b[0]), "r"(b[1]));
}

// ================ mma.sync tf32 GEMM: out = (A @ Bt^T) * dinv ============
template <int N, bool RELU>
__global__ void __launch_bounds__(256)
mma_gcn_kernel(const float* __restrict__ A, const float* __restrict__ Bt,
               const float* __restrict__ dinv, const float* __restrict__ bias,
               float* __restrict__ out1, int M)
{
    constexpr int K  = 128;
    constexpr int P  = 132;
    constexpr int WN = N / 2;
    constexpr int NT = WN / 8;
    extern __shared__ uint32_t smem[];
    uint32_t* As = smem;
    uint32_t* Bs = smem + 128 * P;

    const int tid    = threadIdx.x;
    const int warp   = tid >> 5;
    const int lane   = tid & 31;
    const int warp_m = warp & 3;
    const int warp_n = warp >> 2;
    const int bm     = blockIdx.x * 128;

    #pragma unroll
    for (int it = 0; it < 16; it++) {
        int idx = tid + it * 256;
        int row = idx >> 5;
        int g   = idx & 31;
        int grow = bm + row;
        float4 v = make_float4(0.f, 0.f, 0.f, 0.f);
        if (grow < M) {
            v = *reinterpret_cast<const float4*>(&A[(size_t)grow * K + g * 4]);
            if (RELU) {
                float s = dinv[grow];
                float4 bb = *reinterpret_cast<const float4*>(&bias[g * 4]);
                v.x = fmaxf(fmaf(v.x, s, bb.x), 0.f);
                v.y = fmaxf(fmaf(v.y, s, bb.y), 0.f);
                v.z = fmaxf(fmaf(v.z, s, bb.z), 0.f);
                v.w = fmaxf(fmaf(v.w, s, bb.w), 0.f);
            }
        }
        uint4 u = make_uint4(f2tf32(v.x), f2tf32(v.y), f2tf32(v.z), f2tf32(v.w));
        *reinterpret_cast<uint4*>(&As[row * P + g * 4]) = u;
    }
    #pragma unroll
    for (int it = 0; it < N / 8; it++) {
        int idx = tid + it * 256;
        int row = idx >> 5;
        int g   = idx & 31;
        float4 v = *reinterpret_cast<const float4*>(&Bt[(size_t)row * K + g * 4]);
        uint4 u = make_uint4(f2tf32(v.x), f2tf32(v.y), f2tf32(v.z), f2tf32(v.w));
        *reinterpret_cast<uint4*>(&Bs[row * P + g * 4]) = u;
    }
    __syncthreads();

    float c[2][NT][4];
    #pragma unroll
    for (int mt = 0; mt < 2; mt++)
        #pragma unroll
        for (int nt = 0; nt < NT; nt++)
            #pragma unroll
            for (int j = 0; j < 4; j++) c[mt][nt][j] = 0.f;

    const int lq = lane >> 2;
    const int lr = lane & 3;

    #pragma unroll
    for (int ks = 0; ks < 16; ks++) {
        const int k0 = ks * 8 + lr;
        uint32_t a[2][4];
        #pragma unroll
        for (int mt = 0; mt < 2; mt++) {
            int r = warp_m * 32 + mt * 16 + lq;
            a[mt][0] = As[r * P + k0];
            a[mt][1] = As[(r + 8) * P + k0];
            a[mt][2] = As[r * P + k0 + 4];
            a[mt][3] = As[(r + 8) * P + k0 + 4];
        }
        uint32_t b[NT][2];
        #pragma unroll
        for (int nt = 0; nt < NT; nt++) {
            int n = warp_n * WN + nt * 8 + lq;
            b[nt][0] = Bs[n * P + k0];
            b[nt][1] = Bs[n * P + k0 + 4];
        }
        #pragma unroll
        for (int mt = 0; mt < 2; mt++)
            #pragma unroll
            for (int nt = 0; nt < NT; nt++)
                mma_tf32(c[mt][nt], a[mt], b[nt]);
    }

    #pragma unroll
    for (int mt = 0; mt < 2; mt++) {
        int r0 = bm + warp_m * 32 + mt * 16 + lq;
        int r1 = r0 + 8;
        float s0 = (r0 < M) ? dinv[r0] : 0.f;
        float s1 = (r1 < M) ? dinv[r1] : 0.f;
        #pragma unroll
        for (int nt = 0; nt < NT; nt++) {
            int n = warp_n * WN + nt * 8 + 2 * lr;
            if (r0 < M) {
                float2 v = make_float2(c[mt][nt][0] * s0, c[mt][nt][1] * s0);
                *reinterpret_cast<float2*>(&out1[(size_t)r0 * N + n]) = v;
            }
            if (r1 < M) {
                float2 v = make_float2(c[mt][nt][2] * s1, c[mt][nt][3] * s1);
                *reinterpret_cast<float2*>(&out1[(size_t)r1 * N + n]) = v;
            }
        }
    }
}

// ================= pull-mode aggregation (CSR gather) =================
// 1 warp per node, 128 cols: lane owns float4.
__global__ void __launch_bounds__(256)
gather128_kernel(const float* __restrict__ hs, float* __restrict__ agg, int M)
{
    int gw = (blockIdx.x * blockDim.x + threadIdx.x) >> 5;
    int lane = threadIdx.x & 31;
    if (gw >= M) return;
    const int v   = gw;
    const int beg = g_rowptr[v];
    const int end = beg + g_deg[v];
    const int col = lane * 4;

    float4 acc = *reinterpret_cast<const float4*>(&hs[(size_t)v * D_HID + col]);
    int e = beg;
    for (; e + 4 <= end; e += 4) {
        int s0 = __ldg(&g_csrsrc[e + 0]);
        int s1 = __ldg(&g_csrsrc[e + 1]);
        int s2 = __ldg(&g_csrsrc[e + 2]);
        int s3 = __ldg(&g_csrsrc[e + 3]);
        float4 t0 = *reinterpret_cast<const float4*>(&hs[(size_t)s0 * D_HID + col]);
        float4 t1 = *reinterpret_cast<const float4*>(&hs[(size_t)s1 * D_HID + col]);
        float4 t2 = *reinterpret_cast<const float4*>(&hs[(size_t)s2 * D_HID + col]);
        float4 t3 = *reinterpret_cast<const float4*>(&hs[(size_t)s3 * D_HID + col]);
        acc.x += t0.x + t1.x + t2.x + t3.x;
        acc.y += t0.y + t1.y + t2.y + t3.y;
        acc.z += t0.z + t1.z + t2.z + t3.z;
        acc.w += t0.w + t1.w + t2.w + t3.w;
    }
    for (; e < end; e++) {
        int s = __ldg(&g_csrsrc[e]);
        float4 t = *reinterpret_cast<const float4*>(&hs[(size_t)s * D_HID + col]);
        acc.x += t.x; acc.y += t.y; acc.z += t.z; acc.w += t.w;
    }
    *reinterpret_cast<float4*>(&agg[(size_t)v * D_HID + col]) = acc;
}

// 1 warp per node, 64 cols: lane owns float2; fused final epilogue -> out.
__global__ void __launch_bounds__(256)
gather64_out_kernel(const float* __restrict__ hs, const float* __restrict__ dinv,
                    const float* __restrict__ b2, float* __restrict__ out, int M)
{
    int gw = (blockIdx.x * blockDim.x + threadIdx.x) >> 5;
    int lane = threadIdx.x & 31;
    if (gw >= M) return;
    const int v   = gw;
    const int beg = g_rowptr[v];
    const int end = beg + g_deg[v];
    const int col = lane * 2;

    float2 acc = *reinterpret_cast<const float2*>(&hs[(size_t)v * D_OUT + col]);
    int e = beg;
    for (; e + 4 <= end; e += 4) {
        int s0 = __ldg(&g_csrsrc[e + 0]);
        int s1 = __ldg(&g_csrsrc[e + 1]);
        int s2 = __ldg(&g_csrsrc[e + 2]);
        int s3 = __ldg(&g_csrsrc[e + 3]);
        float2 t0 = *reinterpret_cast<const float2*>(&hs[(size_t)s0 * D_OUT + col]);
        float2 t1 = *reinterpret_cast<const float2*>(&hs[(size_t)s1 * D_OUT + col]);
        float2 t2 = *reinterpret_cast<const float2*>(&hs[(size_t)s2 * D_OUT + col]);
        float2 t3 = *reinterpret_cast<const float2*>(&hs[(size_t)s3 * D_OUT + col]);
        acc.x += t0.x + t1.x + t2.x + t3.x;
        acc.y += t0.y + t1.y + t2.y + t3.y;
    }
    for (; e < end; e++) {
        int s = __ldg(&g_csrsrc[e]);
        float2 t = *reinterpret_cast<const float2*>(&hs[(size_t)s * D_OUT + col]);
        acc.x += t.x; acc.y += t.y;
    }
    float s = dinv[v];
    float2 bb = *reinterpret_cast<const float2*>(&b2[col]);
    float2 r = make_float2(fmaf(acc.x, s, bb.x), fmaf(acc.y, s, bb.y));
    *reinterpret_cast<float2*>(&out[(size_t)v * D_OUT + col]) = r;
}

// ================= launch =================
extern "C" void kernel_launch(void* const* d_in, const int* in_sizes, int n_in,
                              void* d_out, int out_size)
{
    const float* x  = (const float*)d_in[0];
    const int*   ei = (const int*)  d_in[1];
    const float* W1 = (const float*)d_in[2];
    const float* b1 = (const float*)d_in[3];
    const float* W2 = (const float*)d_in[4];
    const float* b2 = (const float*)d_in[5];
    float* out = (float*)d_out;

    const int M = in_sizes[0] / D_IN;
    const int E = in_sizes[1] / 2;
    const int* src = ei;
    const int* dst = ei + E;

    float *p_h1s, *p_agg1, *p_h2s, *p_dinv, *p_Wt1, *p_Wt2;
    cudaGetSymbolAddress((void**)&p_h1s,  g_h1s);
    cudaGetSymbolAddress((void**)&p_agg1, g_agg1);
    cudaGetSymbolAddress((void**)&p_h2s,  g_h2s);
    cudaGetSymbolAddress((void**)&p_dinv, g_dinv);
    cudaGetSymbolAddress((void**)&p_Wt1,  g_Wt1);
    cudaGetSymbolAddress((void**)&p_Wt2,  g_Wt2);

    const int T = 256;
    const int smem1 = (128 + 128) * 132 * 4;
    const int smem2 = (128 + 64) * 132 * 4;
    cudaFuncSetAttribute(mma_gcn_kernel<128, false>,
                         cudaFuncAttributeMaxDynamicSharedMemorySize, smem1);
    cudaFuncSetAttribute(mma_gcn_kernel<64, true>,
                         cudaFuncAttributeMaxDynamicSharedMemorySize, smem2);

    const int ntiles = (M + SCAN_TILE - 1) / SCAN_TILE;

    // 1. degrees + CSR + dinv + weight transpose
    zero_deg_kernel<<<(M + T - 1) / T, T>>>(M);
    deg_kernel<<<(E + T - 1) / T, T>>>(dst, E);
    dinv_kernel<<<(M + T - 1) / T, T>>>(M);
    scan1_kernel<<<ntiles, 256>>>(M);
    scan2_kernel<<<1, 128>>>(ntiles);
    scan3_kernel<<<(M + T - 1) / T, T>>>(M);
    fill_kernel<<<(E + T - 1) / T, T>>>(src, dst, E);
    transpose_w_kernel<<<(D_IN * D_HID + T - 1) / T, T>>>(W1, W2);

    const int nblk = (M + 127) / 128;
    const int gblk = (M + 7) / 8;     // 8 warps per 256-thread block

    // 2. layer 1 GEMM: h1s = (x@W1)*dinv
    mma_gcn_kernel<128, false><<<nblk, 256, smem1>>>(
        x, p_Wt1, p_dinv, nullptr, p_h1s, M);

    // 3. pull-aggregate: agg1[v] = h1s[v] + sum_{s->v} h1s[s]
    gather128_kernel<<<gblk, 256>>>(p_h1s, p_agg1, M);

    // 4+5. layer 2 GEMM with fused relu(agg1*dinv+b1): h2s = (h1@W2)*dinv
    mma_gcn_kernel<64, true><<<nblk, 256, smem2>>>(
        p_agg1, p_Wt2, p_dinv, b1, p_h2s, M);

    // 6+7. pull-aggregate + fused bias -> out
    gather64_out_kernel<<<gblk, 256>>>(p_h2s, p_dinv, b2, out, M);
}

// round 6
// speedup vs baseline: 2.4774x; 1.0612x over previous
#include <cuda_runtime.h>
#include <cuda_fp16.h>
#include <cstdint>

#define D_IN  128
#define D_HID 128
#define D_OUT 64
#define MAXN  100000
#define MAXE  1600000
#define SCAN_TILE 1024
#define MAX_TILES ((MAXN + SCAN_TILE - 1) / SCAN_TILE)   // 98

// ---- scratch ----
__device__ __half g_h1s[MAXN * D_HID];   // (x@W1)*dinv, fp16 messages
__device__ float  g_agg1[MAXN * D_HID];  // pull-aggregated layer-1 (fp32)
__device__ __half g_h2s[MAXN * D_OUT];   // (h1@W2)*dinv, fp16 messages
__device__ float  g_dinv[MAXN];
__device__ int    g_deg[MAXN];
__device__ int    g_rowptr[MAXN];
__device__ int    g_cursor[MAXN];
__device__ int    g_tilesum[MAX_TILES];
__device__ int    g_csrsrc[MAXE];
__device__ float  g_Wt1[D_HID * D_IN];   // [N=128][K=128] K-major (W1^T)
__device__ float  g_Wt2[D_OUT * D_HID];  // [N=64][K=128]  K-major (W2^T)

// ================= degree =================
__global__ void zero_deg_kernel(int n) {
    int i = blockIdx.x * blockDim.x + threadIdx.x;
    if (i < n) g_deg[i] = 0;
}
__global__ void deg_kernel(const int* __restrict__ dst, int E) {
    int e = blockIdx.x * blockDim.x + threadIdx.x;
    if (e < E) atomicAdd(&g_deg[dst[e]], 1);
}

// ================= CSR build: exclusive scan of deg =================
__global__ void __launch_bounds__(256) scan1_kernel(int n) {
    __shared__ int wsum[8];
    const int tid  = threadIdx.x;
    const int lane = tid & 31, wid = tid >> 5;
    const int base = blockIdx.x * SCAN_TILE + tid * 4;

    int v0 = 0, v1 = 0, v2 = 0, v3 = 0;
    if (base + 0 < n) v0 = g_deg[base + 0];
    if (base + 1 < n) v1 = g_deg[base + 1];
    if (base + 2 < n) v2 = g_deg[base + 2];
    if (base + 3 < n) v3 = g_deg[base + 3];
    int tsum = v0 + v1 + v2 + v3;

    int x = tsum;
    #pragma unroll
    for (int o = 1; o < 32; o <<= 1) {
        int y = __shfl_up_sync(0xFFFFFFFFu, x, o);
        if (lane >= o) x += y;
    }
    if (lane == 31) wsum[wid] = x;
    __syncthreads();
    if (wid == 0 && lane < 8) {
        int w = wsum[lane];
        #pragma unroll
        for (int o = 1; o < 8; o <<= 1) {
            int y = __shfl_up_sync(0xFFu, w, o);
            if (lane >= o) w += y;
        }
        wsum[lane] = w;
    }
    __syncthreads();
    int warp_off = (wid == 0) ? 0 : wsum[wid - 1];
    int excl = warp_off + x - tsum;

    if (base + 0 < n) g_rowptr[base + 0] = excl;
    if (base + 1 < n) g_rowptr[base + 1] = excl + v0;
    if (base + 2 < n) g_rowptr[base + 2] = excl + v0 + v1;
    if (base + 3 < n) g_rowptr[base + 3] = excl + v0 + v1 + v2;
    __syncthreads();
    if (tid == 255) g_tilesum[blockIdx.x] = warp_off + x;
}

__global__ void __launch_bounds__(128) scan2_kernel(int ntiles) {
    __shared__ int wsum[4];
    const int tid = threadIdx.x;
    const int lane = tid & 31, wid = tid >> 5;
    int v = (tid < ntiles) ? g_tilesum[tid] : 0;
    int x = v;
    #pragma unroll
    for (int o = 1; o < 32; o <<= 1) {
        int y = __shfl_up_sync(0xFFFFFFFFu, x, o);
        if (lane >= o) x += y;
    }
    if (lane == 31) wsum[wid] = x;
    __syncthreads();
    if (wid == 0 && lane < 4) {
        int w = wsum[lane];
        #pragma unroll
        for (int o = 1; o < 4; o <<= 1) {
            int y = __shfl_up_sync(0xFu, w, o);
            if (lane >= o) w += y;
        }
        wsum[lane] = w;
    }
    __syncthreads();
    int warp_off = (wid == 0) ? 0 : wsum[wid - 1];
    if (tid < ntiles) g_tilesum[tid] = warp_off + x - v;
}

// scan3: add tile offsets; init cursor; compute dinv (fused)
__global__ void scan3_kernel(int n) {
    int i = blockIdx.x * blockDim.x + threadIdx.x;
    if (i < n) {
        int r = g_rowptr[i] + g_tilesum[i >> 10];
        g_rowptr[i] = r;
        g_cursor[i] = r;
        g_dinv[i] = rsqrtf((float)(g_deg[i] + 1));
    }
}

__global__ void fill_kernel(const int* __restrict__ src,
                            const int* __restrict__ dst, int E) {
    int e = blockIdx.x * blockDim.x + threadIdx.x;
    if (e < E) {
        int pos = atomicAdd(&g_cursor[dst[e]], 1);
        g_csrsrc[pos] = src[e];
    }
}

// ================= weight transpose =================
__global__ void transpose_w_kernel(const float* __restrict__ W1,
                                   const float* __restrict__ W2) {
    int i = blockIdx.x * blockDim.x + threadIdx.x;
    if (i < D_IN * D_HID) {
        int k = i / D_HID, n = i % D_HID;
        g_Wt1[n * D_IN + k] = W1[k * D_HID + n];
    }
    if (i < D_HID * D_OUT) {
        int k = i / D_OUT, n = i % D_OUT;
        g_Wt2[n * D_HID + k] = W2[k * D_OUT + n];
    }
}

// ================= tf32 helpers =================
__device__ __forceinline__ uint32_t f2tf32(float f) {
    uint32_t u;
    asm("cvt.rna.tf32.f32 %0, %1;" : "=r"(u) : "f"(f));
    return u;
}
__device__ __forceinline__ void mma_tf32(float* c, const uint32_t* a,
                                         const uint32_t* b) {
    asm volatile(
        "mma.sync.aligned.m16n8k8.row.col.f32.tf32.tf32.f32 "
        "{%0,%1,%2,%3}, {%4,%5,%6,%7}, {%8,%9}, {%0,%1,%2,%3};"
        : "+f"(c[0]), "+f"(c[1]), "+f"(c[2]), "+f"(c[3])
        : "r"(a[0]), "r"(a[1]), "r"(a[2]), "r"(a[3]), "r"(b[0]), "r"(b[1]));
}

// ============ mma.sync tf32 GEMM: out = half{(A @ Bt^T) * dinv} ==========
// A: [M,128] fp32 row-major (optional fused relu(a*dinv+bias) on load)
// Bt: [N,128] fp32 K-major.  out: [M,N] fp16
template <int N, bool RELU>
__global__ void __launch_bounds__(256)
mma_gcn_kernel(const float* __restrict__ A, const float* __restrict__ Bt,
               const float* __restrict__ dinv, const float* __restrict__ bias,
               __half* __restrict__ out, int M)
{
    constexpr int K  = 128;
    constexpr int P  = 132;
    constexpr int WN = N / 2;
    constexpr int NT = WN / 8;
    extern __shared__ uint32_t smem[];
    uint32_t* As = smem;
    uint32_t* Bs = smem + 128 * P;

    const int tid    = threadIdx.x;
    const int warp   = tid >> 5;
    const int lane   = tid & 31;
    const int warp_m = warp & 3;
    const int warp_n = warp >> 2;
    const int bm     = blockIdx.x * 128;

    #pragma unroll
    for (int it = 0; it < 16; it++) {
        int idx = tid + it * 256;
        int row = idx >> 5;
        int g   = idx & 31;
        int grow = bm + row;
        float4 v = make_float4(0.f, 0.f, 0.f, 0.f);
        if (grow < M) {
            v = *reinterpret_cast<const float4*>(&A[(size_t)grow * K + g * 4]);
            if (RELU) {
                float s = dinv[grow];
                float4 bb = *reinterpret_cast<const float4*>(&bias[g * 4]);
                v.x = fmaxf(fmaf(v.x, s, bb.x), 0.f);
                v.y = fmaxf(fmaf(v.y, s, bb.y), 0.f);
                v.z = fmaxf(fmaf(v.z, s, bb.z), 0.f);
                v.w = fmaxf(fmaf(v.w, s, bb.w), 0.f);
            }
        }
        uint4 u = make_uint4(f2tf32(v.x), f2tf32(v.y), f2tf32(v.z), f2tf32(v.w));
        *reinterpret_cast<uint4*>(&As[row * P + g * 4]) = u;
    }
    #pragma unroll
    for (int it = 0; it < N / 8; it++) {
        int idx = tid + it * 256;
        int row = idx >> 5;
        int g   = idx & 31;
        float4 v = *reinterpret_cast<const float4*>(&Bt[(size_t)row * K + g * 4]);
        uint4 u = make_uint4(f2tf32(v.x), f2tf32(v.y), f2tf32(v.z), f2tf32(v.w));
        *reinterpret_cast<uint4*>(&Bs[row * P + g * 4]) = u;
    }
    __syncthreads();

    float c[2][NT][4];
    #pragma unroll
    for (int mt = 0; mt < 2; mt++)
        #pragma unroll
        for (int nt = 0; nt < NT; nt++)
            #pragma unroll
            for (int j = 0; j < 4; j++) c[mt][nt][j] = 0.f;

    const int lq = lane >> 2;
    const int lr = lane & 3;

    #pragma unroll
    for (int ks = 0; ks < 16; ks++) {
        const int k0 = ks * 8 + lr;
        uint32_t a[2][4];
        #pragma unroll
        for (int mt = 0; mt < 2; mt++) {
            int r = warp_m * 32 + mt * 16 + lq;
            a[mt][0] = As[r * P + k0];
            a[mt][1] = As[(r + 8) * P + k0];
            a[mt][2] = As[r * P + k0 + 4];
            a[mt][3] = As[(r + 8) * P + k0 + 4];
        }
        uint32_t b[NT][2];
        #pragma unroll
        for (int nt = 0; nt < NT; nt++) {
            int n = warp_n * WN + nt * 8 + lq;
            b[nt][0] = Bs[n * P + k0];
            b[nt][1] = Bs[n * P + k0 + 4];
        }
        #pragma unroll
        for (int mt = 0; mt < 2; mt++)
            #pragma unroll
            for (int nt = 0; nt < NT; nt++)
                mma_tf32(c[mt][nt], a[mt], b[nt]);
    }

    // ---- epilogue: dinv scale -> fp16 store ----
    #pragma unroll
    for (int mt = 0; mt < 2; mt++) {
        int r0 = bm + warp_m * 32 + mt * 16 + lq;
        int r1 = r0 + 8;
        float s0 = (r0 < M) ? dinv[r0] : 0.f;
        float s1 = (r1 < M) ? dinv[r1] : 0.f;
        #pragma unroll
        for (int nt = 0; nt < NT; nt++) {
            int n = warp_n * WN + nt * 8 + 2 * lr;
            if (r0 < M) {
                __half2 h = __floats2half2_rn(c[mt][nt][0] * s0, c[mt][nt][1] * s0);
                *reinterpret_cast<__half2*>(&out[(size_t)r0 * N + n]) = h;
            }
            if (r1 < M) {
                __half2 h = __floats2half2_rn(c[mt][nt][2] * s1, c[mt][nt][3] * s1);
                *reinterpret_cast<__half2*>(&out[(size_t)r1 * N + n]) = h;
            }
        }
    }
}

// ================= pull-mode aggregation (CSR gather, fp16 src) =========
__device__ __forceinline__ float4 h4_to_f4(uint2 u) {
    __half2 h0 = *reinterpret_cast<__half2*>(&u.x);
    __half2 h1 = *reinterpret_cast<__half2*>(&u.y);
    float2 f0 = __half22float2(h0);
    float2 f1 = __half22float2(h1);
    return make_float4(f0.x, f0.y, f1.x, f1.y);
}

// 1 warp per node, 128 cols: lane owns 4 halves (8B). agg out fp32.
__global__ void __launch_bounds__(256)
gather128_kernel(const __half* __restrict__ hs, float* __restrict__ agg, int M)
{
    int gw = (blockIdx.x * blockDim.x + threadIdx.x) >> 5;
    int lane = threadIdx.x & 31;
    if (gw >= M) return;
    const int v   = gw;
    const int beg = g_rowptr[v];
    const int end = beg + g_deg[v];
    const int col = lane * 4;

    float4 acc = h4_to_f4(*reinterpret_cast<const uint2*>(&hs[(size_t)v * D_HID + col]));
    int e = beg;
    for (; e + 4 <= end; e += 4) {
        int s0 = __ldg(&g_csrsrc[e + 0]);
        int s1 = __ldg(&g_csrsrc[e + 1]);
        int s2 = __ldg(&g_csrsrc[e + 2]);
        int s3 = __ldg(&g_csrsrc[e + 3]);
        float4 t0 = h4_to_f4(*reinterpret_cast<const uint2*>(&hs[(size_t)s0 * D_HID + col]));
        float4 t1 = h4_to_f4(*reinterpret_cast<const uint2*>(&hs[(size_t)s1 * D_HID + col]));
        float4 t2 = h4_to_f4(*reinterpret_cast<const uint2*>(&hs[(size_t)s2 * D_HID + col]));
        float4 t3 = h4_to_f4(*reinterpret_cast<const uint2*>(&hs[(size_t)s3 * D_HID + col]));
        acc.x += t0.x + t1.x + t2.x + t3.x;
        acc.y += t0.y + t1.y + t2.y + t3.y;
        acc.z += t0.z + t1.z + t2.z + t3.z;
        acc.w += t0.w + t1.w + t2.w + t3.w;
    }
    for (; e < end; e++) {
        int s = __ldg(&g_csrsrc[e]);
        float4 t = h4_to_f4(*reinterpret_cast<const uint2*>(&hs[(size_t)s * D_HID + col]));
        acc.x += t.x; acc.y += t.y; acc.z += t.z; acc.w += t.w;
    }
    *reinterpret_cast<float4*>(&agg[(size_t)v * D_HID + col]) = acc;
}

// 1 warp per node, 64 cols: lane owns 2 halves (4B); fused epilogue -> out.
__global__ void __launch_bounds__(256)
gather64_out_kernel(const __half* __restrict__ hs, const float* __restrict__ dinv,
                    const float* __restrict__ b2, float* __restrict__ out, int M)
{
    int gw = (blockIdx.x * blockDim.x + threadIdx.x) >> 5;
    int lane = threadIdx.x & 31;
    if (gw >= M) return;
    const int v   = gw;
    const int beg = g_rowptr[v];
    const int end = beg + g_deg[v];
    const int col = lane * 2;

    float2 acc = __half22float2(*reinterpret_cast<const __half2*>(&hs[(size_t)v * D_OUT + col]));
    int e = beg;
    for (; e + 4 <= end; e += 4) {
        int s0 = __ldg(&g_csrsrc[e + 0]);
        int s1 = __ldg(&g_csrsrc[e + 1]);
        int s2 = __ldg(&g_csrsrc[e + 2]);
        int s3 = __ldg(&g_csrsrc[e + 3]);
        float2 t0 = __half22float2(*reinterpret_cast<const __half2*>(&hs[(size_t)s0 * D_OUT + col]));
        float2 t1 = __half22float2(*reinterpret_cast<const __half2*>(&hs[(size_t)s1 * D_OUT + col]));
        float2 t2 = __half22float2(*reinterpret_cast<const __half2*>(&hs[(size_t)s2 * D_OUT + col]));
        float2 t3 = __half22float2(*reinterpret_cast<const __half2*>(&hs[(size_t)s3 * D_OUT + col]));
        acc.x += t0.x + t1.x + t2.x + t3.x;
        acc.y += t0.y + t1.y + t2.y + t3.y;
    }
    for (; e < end; e++) {
        int s = __ldg(&g_csrsrc[e]);
        float2 t = __half22float2(*reinterpret_cast<const __half2*>(&hs[(size_t)s * D_OUT + col]));
        acc.x += t.x; acc.y += t.y;
    }
    float s = dinv[v];
    float2 bb = *reinterpret_cast<const float2*>(&b2[col]);
    float2 r = make_float2(fmaf(acc.x, s, bb.x), fmaf(acc.y, s, bb.y));
    *reinterpret_cast<float2*>(&out[(size_t)v * D_OUT + col]) = r;
}

// ================= launch =================
extern "C" void kernel_launch(void* const* d_in, const int* in_sizes, int n_in,
                              void* d_out, int out_size)
{
    const float* x  = (const float*)d_in[0];
    const int*   ei = (const int*)  d_in[1];
    const float* W1 = (const float*)d_in[2];
    const float* b1 = (const float*)d_in[3];
    const float* W2 = (const float*)d_in[4];
    const float* b2 = (const float*)d_in[5];
    float* out = (float*)d_out;

    const int M = in_sizes[0] / D_IN;
    const int E = in_sizes[1] / 2;
    const int* src = ei;
    const int* dst = ei + E;

    __half *p_h1s, *p_h2s;
    float *p_agg1, *p_dinv, *p_Wt1, *p_Wt2;
    cudaGetSymbolAddress((void**)&p_h1s,  g_h1s);
    cudaGetSymbolAddress((void**)&p_agg1, g_agg1);
    cudaGetSymbolAddress((void**)&p_h2s,  g_h2s);
    cudaGetSymbolAddress((void**)&p_dinv, g_dinv);
    cudaGetSymbolAddress((void**)&p_Wt1,  g_Wt1);
    cudaGetSymbolAddress((void**)&p_Wt2,  g_Wt2);

    const int T = 256;
    const int smem1 = (128 + 128) * 132 * 4;
    const int smem2 = (128 + 64) * 132 * 4;
    cudaFuncSetAttribute(mma_gcn_kernel<128, false>,
                         cudaFuncAttributeMaxDynamicSharedMemorySize, smem1);
    cudaFuncSetAttribute(mma_gcn_kernel<64, true>,
                         cudaFuncAttributeMaxDynamicSharedMemorySize, smem2);

    const int ntiles = (M + SCAN_TILE - 1) / SCAN_TILE;

    // 1. degrees + CSR + dinv + weight transpose
    zero_deg_kernel<<<(M + T - 1) / T, T>>>(M);
    deg_kernel<<<(E + T - 1) / T, T>>>(dst, E);
    scan1_kernel<<<ntiles, 256>>>(M);
    scan2_kernel<<<1, 128>>>(ntiles);
    scan3_kernel<<<(M + T - 1) / T, T>>>(M);
    fill_kernel<<<(E + T - 1) / T, T>>>(src, dst, E);
    transpose_w_kernel<<<(D_IN * D_HID + T - 1) / T, T>>>(W1, W2);

    const int nblk = (M + 127) / 128;
    const int gblk = (M + 7) / 8;

    // 2. layer 1 GEMM: h1s = fp16{(x@W1)*dinv}
    mma_gcn_kernel<128, false><<<nblk, 256, smem1>>>(
        x, p_Wt1, p_dinv, nullptr, p_h1s, M);

    // 3. pull-aggregate (fp16 msgs, fp32 accum): agg1[v] = h1s[v] + sum h1s[s]
    gather128_kernel<<<gblk, 256>>>(p_h1s, p_agg1, M);

    // 4+5. layer 2 GEMM with fused relu(agg1*dinv+b1): h2s = fp16{(h1@W2)*dinv}
    mma_gcn_kernel<64, true><<<nblk, 256, smem2>>>(
        p_agg1, p_Wt2, p_dinv, b1, p_h2s, M);

    // 6+7. pull-aggregate + fused bias -> out (fp32)
    gather64_out_kernel<<<gblk, 256>>>(p_h2s, p_dinv, b2, out, M);
}

// round 7
// speedup vs baseline: 2.4817x; 1.0017x over previous
#include <cuda_runtime.h>
#include <cuda_fp16.h>
#include <cstdint>

#define D_IN  128
#define D_HID 128
#define D_OUT 64
#define MAXN  100000
#define MAXE  1600000
#define SCAN_TILE 1024
#define MAX_TILES ((MAXN + SCAN_TILE - 1) / SCAN_TILE)   // 98

// ---- scratch ----
__device__ __half g_h1s[MAXN * D_HID];   // x@W1 (UNscaled), fp16 messages
__device__ float  g_agg1[MAXN * D_HID];  // pull-aggregated layer-1 (fp32)
__device__ __half g_h2s[MAXN * D_OUT];   // (h1@W2)*dinv, fp16 messages
__device__ float  g_dinv[MAXN];
__device__ int    g_deg[MAXN];
__device__ int    g_rowptr[MAXN];
__device__ int    g_cursor[MAXN];
__device__ int    g_tilesum[MAX_TILES];
__device__ int    g_csrsrc[MAXE];
__device__ float  g_Wt1[D_HID * D_IN];   // [N=128][K=128] K-major (W1^T)
__device__ float  g_Wt2[D_OUT * D_HID];  // [N=64][K=128]  K-major (W2^T)

// ================= degree =================
__global__ void zero_deg_kernel(int n) {
    int i = blockIdx.x * blockDim.x + threadIdx.x;
    if (i < n) g_deg[i] = 0;
}
__global__ void deg_kernel(const int* __restrict__ dst, int E) {
    int e = blockIdx.x * blockDim.x + threadIdx.x;
    if (e < E) atomicAdd(&g_deg[dst[e]], 1);
}

// ================= CSR build: exclusive scan of deg =================
__global__ void __launch_bounds__(256) scan1_kernel(int n) {
    __shared__ int wsum[8];
    const int tid  = threadIdx.x;
    const int lane = tid & 31, wid = tid >> 5;
    const int base = blockIdx.x * SCAN_TILE + tid * 4;

    int v0 = 0, v1 = 0, v2 = 0, v3 = 0;
    if (base + 0 < n) v0 = g_deg[base + 0];
    if (base + 1 < n) v1 = g_deg[base + 1];
    if (base + 2 < n) v2 = g_deg[base + 2];
    if (base + 3 < n) v3 = g_deg[base + 3];
    int tsum = v0 + v1 + v2 + v3;

    int x = tsum;
    #pragma unroll
    for (int o = 1; o < 32; o <<= 1) {
        int y = __shfl_up_sync(0xFFFFFFFFu, x, o);
        if (lane >= o) x += y;
    }
    if (lane == 31) wsum[wid] = x;
    __syncthreads();
    if (wid == 0 && lane < 8) {
        int w = wsum[lane];
        #pragma unroll
        for (int o = 1; o < 8; o <<= 1) {
            int y = __shfl_up_sync(0xFFu, w, o);
            if (lane >= o) w += y;
        }
        wsum[lane] = w;
    }
    __syncthreads();
    int warp_off = (wid == 0) ? 0 : wsum[wid - 1];
    int excl = warp_off + x - tsum;

    if (base + 0 < n) g_rowptr[base + 0] = excl;
    if (base + 1 < n) g_rowptr[base + 1] = excl + v0;
    if (base + 2 < n) g_rowptr[base + 2] = excl + v0 + v1;
    if (base + 3 < n) g_rowptr[base + 3] = excl + v0 + v1 + v2;
    __syncthreads();
    if (tid == 255) g_tilesum[blockIdx.x] = warp_off + x;
}

__global__ void __launch_bounds__(128) scan2_kernel(int ntiles) {
    __shared__ int wsum[4];
    const int tid = threadIdx.x;
    const int lane = tid & 31, wid = tid >> 5;
    int v = (tid < ntiles) ? g_tilesum[tid] : 0;
    int x = v;
    #pragma unroll
    for (int o = 1; o < 32; o <<= 1) {
        int y = __shfl_up_sync(0xFFFFFFFFu, x, o);
        if (lane >= o) x += y;
    }
    if (lane == 31) wsum[wid] = x;
    __syncthreads();
    if (wid == 0 && lane < 4) {
        int w = wsum[lane];
        #pragma unroll
        for (int o = 1; o < 4; o <<= 1) {
            int y = __shfl_up_sync(0xFu, w, o);
            if (lane >= o) w += y;
        }
        wsum[lane] = w;
    }
    __syncthreads();
    int warp_off = (wid == 0) ? 0 : wsum[wid - 1];
    if (tid < ntiles) g_tilesum[tid] = warp_off + x - v;
}

// scan3: add tile offsets; init cursor; compute dinv (fused)
__global__ void scan3_kernel(int n) {
    int i = blockIdx.x * blockDim.x + threadIdx.x;
    if (i < n) {
        int r = g_rowptr[i] + g_tilesum[i >> 10];
        g_rowptr[i] = r;
        g_cursor[i] = r;
        g_dinv[i] = rsqrtf((float)(g_deg[i] + 1));
    }
}

__global__ void fill_kernel(const int* __restrict__ src,
                            const int* __restrict__ dst, int E) {
    int e = blockIdx.x * blockDim.x + threadIdx.x;
    if (e < E) {
        int pos = atomicAdd(&g_cursor[dst[e]], 1);
        g_csrsrc[pos] = src[e];
    }
}

// ================= weight transpose =================
__global__ void transpose_w_kernel(const float* __restrict__ W1,
                                   const float* __restrict__ W2) {
    int i = blockIdx.x * blockDim.x + threadIdx.x;
    if (i < D_IN * D_HID) {
        int k = i / D_HID, n = i % D_HID;
        g_Wt1[n * D_IN + k] = W1[k * D_HID + n];
    }
    if (i < D_HID * D_OUT) {
        int k = i / D_OUT, n = i % D_OUT;
        g_Wt2[n * D_HID + k] = W2[k * D_OUT + n];
    }
}

// ================= tf32 helpers =================
__device__ __forceinline__ uint32_t f2tf32(float f) {
    uint32_t u;
    asm("cvt.rna.tf32.f32 %0, %1;" : "=r"(u) : "f"(f));
    return u;
}
__device__ __forceinline__ void mma_tf32(float* c, const uint32_t* a,
                                         const uint32_t* b) {
    asm volatile(
        "mma.sync.aligned.m16n8k8.row.col.f32.tf32.tf32.f32 "
        "{%0,%1,%2,%3}, {%4,%5,%6,%7}, {%8,%9}, {%0,%1,%2,%3};"
        : "+f"(c[0]), "+f"(c[1]), "+f"(c[2]), "+f"(c[3])
        : "r"(a[0]), "r"(a[1]), "r"(a[2]), "r"(a[3]), "r"(b[0]), "r"(b[1]));
}

// ============ mma.sync tf32 GEMM ============
// out = fp16{ (A @ Bt^T) * (SCALE ? dinv : 1) },  A optionally relu(a*dinv+bias)
template <int N, bool RELU, bool SCALE>
__global__ void __launch_bounds__(256)
mma_gcn_kernel(const float* __restrict__ A, const float* __restrict__ Bt,
               const float* __restrict__ dinv, const float* __restrict__ bias,
               __half* __restrict__ out, int M)
{
    constexpr int K  = 128;
    constexpr int P  = 132;
    constexpr int WN = N / 2;
    constexpr int NT = WN / 8;
    extern __shared__ uint32_t smem[];
    uint32_t* As = smem;
    uint32_t* Bs = smem + 128 * P;

    const int tid    = threadIdx.x;
    const int warp   = tid >> 5;
    const int lane   = tid & 31;
    const int warp_m = warp & 3;
    const int warp_n = warp >> 2;
    const int bm     = blockIdx.x * 128;

    #pragma unroll
    for (int it = 0; it < 16; it++) {
        int idx = tid + it * 256;
        int row = idx >> 5;
        int g   = idx & 31;
        int grow = bm + row;
        float4 v = make_float4(0.f, 0.f, 0.f, 0.f);
        if (grow < M) {
            v = *reinterpret_cast<const float4*>(&A[(size_t)grow * K + g * 4]);
            if (RELU) {
                float s = dinv[grow];
                float4 bb = *reinterpret_cast<const float4*>(&bias[g * 4]);
                v.x = fmaxf(fmaf(v.x, s, bb.x), 0.f);
                v.y = fmaxf(fmaf(v.y, s, bb.y), 0.f);
                v.z = fmaxf(fmaf(v.z, s, bb.z), 0.f);
                v.w = fmaxf(fmaf(v.w, s, bb.w), 0.f);
            }
        }
        uint4 u = make_uint4(f2tf32(v.x), f2tf32(v.y), f2tf32(v.z), f2tf32(v.w));
        *reinterpret_cast<uint4*>(&As[row * P + g * 4]) = u;
    }
    #pragma unroll
    for (int it = 0; it < N / 8; it++) {
        int idx = tid + it * 256;
        int row = idx >> 5;
        int g   = idx & 31;
        float4 v = *reinterpret_cast<const float4*>(&Bt[(size_t)row * K + g * 4]);
        uint4 u = make_uint4(f2tf32(v.x), f2tf32(v.y), f2tf32(v.z), f2tf32(v.w));
        *reinterpret_cast<uint4*>(&Bs[row * P + g * 4]) = u;
    }
    __syncthreads();

    float c[2][NT][4];
    #pragma unroll
    for (int mt = 0; mt < 2; mt++)
        #pragma unroll
        for (int nt = 0; nt < NT; nt++)
            #pragma unroll
            for (int j = 0; j < 4; j++) c[mt][nt][j] = 0.f;

    const int lq = lane >> 2;
    const int lr = lane & 3;

    #pragma unroll
    for (int ks = 0; ks < 16; ks++) {
        const int k0 = ks * 8 + lr;
        uint32_t a[2][4];
        #pragma unroll
        for (int mt = 0; mt < 2; mt++) {
            int r = warp_m * 32 + mt * 16 + lq;
            a[mt][0] = As[r * P + k0];
            a[mt][1] = As[(r + 8) * P + k0];
            a[mt][2] = As[r * P + k0 + 4];
            a[mt][3] = As[(r + 8) * P + k0 + 4];
        }
        uint32_t b[NT][2];
        #pragma unroll
        for (int nt = 0; nt < NT; nt++) {
            int n = warp_n * WN + nt * 8 + lq;
            b[nt][0] = Bs[n * P + k0];
            b[nt][1] = Bs[n * P + k0 + 4];
        }
        #pragma unroll
        for (int mt = 0; mt < 2; mt++)
            #pragma unroll
            for (int nt = 0; nt < NT; nt++)
                mma_tf32(c[mt][nt], a[mt], b[nt]);
    }

    // ---- epilogue: optional dinv scale -> fp16 store ----
    #pragma unroll
    for (int mt = 0; mt < 2; mt++) {
        int r0 = bm + warp_m * 32 + mt * 16 + lq;
        int r1 = r0 + 8;
        float s0 = 1.f, s1 = 1.f;
        if (SCALE) {
            s0 = (r0 < M) ? dinv[r0] : 0.f;
            s1 = (r1 < M) ? dinv[r1] : 0.f;
        }
        #pragma unroll
        for (int nt = 0; nt < NT; nt++) {
            int n = warp_n * WN + nt * 8 + 2 * lr;
            if (r0 < M) {
                __half2 h = __floats2half2_rn(c[mt][nt][0] * s0, c[mt][nt][1] * s0);
                *reinterpret_cast<__half2*>(&out[(size_t)r0 * N + n]) = h;
            }
            if (r1 < M) {
                __half2 h = __floats2half2_rn(c[mt][nt][2] * s1, c[mt][nt][3] * s1);
                *reinterpret_cast<__half2*>(&out[(size_t)r1 * N + n]) = h;
            }
        }
    }
}

// ================= pull-mode aggregation (CSR gather, fp16 src) =========
__device__ __forceinline__ float4 h4_to_f4(uint2 u) {
    __half2 h0 = *reinterpret_cast<__half2*>(&u.x);
    __half2 h1 = *reinterpret_cast<__half2*>(&u.y);
    float2 f0 = __half22float2(h0);
    float2 f1 = __half22float2(h1);
    return make_float4(f0.x, f0.y, f1.x, f1.y);
}

// 1 warp per node, 128 cols. hs is UNscaled; applies dinv[s] per message:
//   agg[v] = dinv[v]*hs[v] + sum_s dinv[s]*hs[s]
__global__ void __launch_bounds__(256)
gather128_kernel(const __half* __restrict__ hs, const float* __restrict__ dinv,
                 float* __restrict__ agg, int M)
{
    int gw = (blockIdx.x * blockDim.x + threadIdx.x) >> 5;
    int lane = threadIdx.x & 31;
    if (gw >= M) return;
    const int v   = gw;
    const int beg = g_rowptr[v];
    const int end = beg + g_deg[v];
    const int col = lane * 4;

    float dv = dinv[v];
    float4 t = h4_to_f4(*reinterpret_cast<const uint2*>(&hs[(size_t)v * D_HID + col]));
    float4 acc = make_float4(dv * t.x, dv * t.y, dv * t.z, dv * t.w);
    int e = beg;
    for (; e + 4 <= end; e += 4) {
        int s0 = __ldg(&g_csrsrc[e + 0]);
        int s1 = __ldg(&g_csrsrc[e + 1]);
        int s2 = __ldg(&g_csrsrc[e + 2]);
        int s3 = __ldg(&g_csrsrc[e + 3]);
        float d0 = __ldg(&dinv[s0]);
        float d1 = __ldg(&dinv[s1]);
        float d2 = __ldg(&dinv[s2]);
        float d3 = __ldg(&dinv[s3]);
        float4 t0 = h4_to_f4(*reinterpret_cast<const uint2*>(&hs[(size_t)s0 * D_HID + col]));
        float4 t1 = h4_to_f4(*reinterpret_cast<const uint2*>(&hs[(size_t)s1 * D_HID + col]));
        float4 t2 = h4_to_f4(*reinterpret_cast<const uint2*>(&hs[(size_t)s2 * D_HID + col]));
        float4 t3 = h4_to_f4(*reinterpret_cast<const uint2*>(&hs[(size_t)s3 * D_HID + col]));
        acc.x = fmaf(d0, t0.x, fmaf(d1, t1.x, fmaf(d2, t2.x, fmaf(d3, t3.x, acc.x))));
        acc.y = fmaf(d0, t0.y, fmaf(d1, t1.y, fmaf(d2, t2.y, fmaf(d3, t3.y, acc.y))));
        acc.z = fmaf(d0, t0.z, fmaf(d1, t1.z, fmaf(d2, t2.z, fmaf(d3, t3.z, acc.z))));
        acc.w = fmaf(d0, t0.w, fmaf(d1, t1.w, fmaf(d2, t2.w, fmaf(d3, t3.w, acc.w))));
    }
    for (; e < end; e++) {
        int s = __ldg(&g_csrsrc[e]);
        float d = __ldg(&dinv[s]);
        float4 tt = h4_to_f4(*reinterpret_cast<const uint2*>(&hs[(size_t)s * D_HID + col]));
        acc.x = fmaf(d, tt.x, acc.x);
        acc.y = fmaf(d, tt.y, acc.y);
        acc.z = fmaf(d, tt.z, acc.z);
        acc.w = fmaf(d, tt.w, acc.w);
    }
    *reinterpret_cast<float4*>(&agg[(size_t)v * D_HID + col]) = acc;
}

// 1 warp per node, 64 cols; hs pre-scaled by dinv; fused epilogue -> out.
__global__ void __launch_bounds__(256)
gather64_out_kernel(const __half* __restrict__ hs, const float* __restrict__ dinv,
                    const float* __restrict__ b2, float* __restrict__ out, int M)
{
    int gw = (blockIdx.x * blockDim.x + threadIdx.x) >> 5;
    int lane = threadIdx.x & 31;
    if (gw >= M) return;
    const int v   = gw;
    const int beg = g_rowptr[v];
    const int end = beg + g_deg[v];
    const int col = lane * 2;

    float2 acc = __half22float2(*reinterpret_cast<const __half2*>(&hs[(size_t)v * D_OUT + col]));
    int e = beg;
    for (; e + 4 <= end; e += 4) {
        int s0 = __ldg(&g_csrsrc[e + 0]);
        int s1 = __ldg(&g_csrsrc[e + 1]);
        int s2 = __ldg(&g_csrsrc[e + 2]);
        int s3 = __ldg(&g_csrsrc[e + 3]);
        float2 t0 = __half22float2(*reinterpret_cast<const __half2*>(&hs[(size_t)s0 * D_OUT + col]));
        float2 t1 = __half22float2(*reinterpret_cast<const __half2*>(&hs[(size_t)s1 * D_OUT + col]));
        float2 t2 = __half22float2(*reinterpret_cast<const __half2*>(&hs[(size_t)s2 * D_OUT + col]));
        float2 t3 = __half22float2(*reinterpret_cast<const __half2*>(&hs[(size_t)s3 * D_OUT + col]));
        acc.x += t0.x + t1.x + t2.x + t3.x;
        acc.y += t0.y + t1.y + t2.y + t3.y;
    }
    for (; e < end; e++) {
        int s = __ldg(&g_csrsrc[e]);
        float2 t = __half22float2(*reinterpret_cast<const __half2*>(&hs[(size_t)s * D_OUT + col]));
        acc.x += t.x; acc.y += t.y;
    }
    float s = dinv[v];
    float2 bb = *reinterpret_cast<const float2*>(&b2[col]);
    float2 r = make_float2(fmaf(acc.x, s, bb.x), fmaf(acc.y, s, bb.y));
    *reinterpret_cast<float2*>(&out[(size_t)v * D_OUT + col]) = r;
}

// ================= launch =================
extern "C" void kernel_launch(void* const* d_in, const int* in_sizes, int n_in,
                              void* d_out, int out_size)
{
    const float* x  = (const float*)d_in[0];
    const int*   ei = (const int*)  d_in[1];
    const float* W1 = (const float*)d_in[2];
    const float* b1 = (const float*)d_in[3];
    const float* W2 = (const float*)d_in[4];
    const float* b2 = (const float*)d_in[5];
    float* out = (float*)d_out;

    const int M = in_sizes[0] / D_IN;
    const int E = in_sizes[1] / 2;
    const int* src = ei;
    const int* dst = ei + E;

    __half *p_h1s, *p_h2s;
    float *p_agg1, *p_dinv, *p_Wt1, *p_Wt2;
    cudaGetSymbolAddress((void**)&p_h1s,  g_h1s);
    cudaGetSymbolAddress((void**)&p_agg1, g_agg1);
    cudaGetSymbolAddress((void**)&p_h2s,  g_h2s);
    cudaGetSymbolAddress((void**)&p_dinv, g_dinv);
    cudaGetSymbolAddress((void**)&p_Wt1,  g_Wt1);
    cudaGetSymbolAddress((void**)&p_Wt2,  g_Wt2);

    // one-time handle init (no device memory involved; identical work per call)
    static cudaStream_t s2 = nullptr;
    static cudaEvent_t evFork = nullptr, evJoin = nullptr;
    if (s2 == nullptr) {
        cudaStreamCreateWithFlags(&s2, cudaStreamNonBlocking);
        cudaEventCreateWithFlags(&evFork, cudaEventDisableTiming);
        cudaEventCreateWithFlags(&evJoin, cudaEventDisableTiming);
    }

    const int T = 256;
    const int smem1 = (128 + 128) * 132 * 4;
    const int smem2 = (128 + 64) * 132 * 4;
    cudaFuncSetAttribute(mma_gcn_kernel<128, false, false>,
                         cudaFuncAttributeMaxDynamicSharedMemorySize, smem1);
    cudaFuncSetAttribute(mma_gcn_kernel<64, true, true>,
                         cudaFuncAttributeMaxDynamicSharedMemorySize, smem2);

    const int ntiles = (M + SCAN_TILE - 1) / SCAN_TILE;
    const int nblk = (M + 127) / 128;
    const int gblk = (M + 7) / 8;

    // ---- fork: CSR/degree chain on s2, GEMM1 chain on main stream ----
    cudaEventRecord(evFork, 0);
    cudaStreamWaitEvent(s2, evFork, 0);

    // stream s2: degrees + CSR + dinv
    zero_deg_kernel<<<(M + T - 1) / T, T, 0, s2>>>(M);
    deg_kernel<<<(E + T - 1) / T, T, 0, s2>>>(dst, E);
    scan1_kernel<<<ntiles, 256, 0, s2>>>(M);
    scan2_kernel<<<1, 128, 0, s2>>>(ntiles);
    scan3_kernel<<<(M + T - 1) / T, T, 0, s2>>>(M);
    fill_kernel<<<(E + T - 1) / T, T, 0, s2>>>(src, dst, E);
    cudaEventRecord(evJoin, s2);

    // main stream: weight transpose + layer-1 GEMM (no dinv dependency)
    transpose_w_kernel<<<(D_IN * D_HID + T - 1) / T, T>>>(W1, W2);
    mma_gcn_kernel<128, false, false><<<nblk, 256, smem1>>>(
        x, p_Wt1, nullptr, nullptr, p_h1s, M);

    // ---- join ----
    cudaStreamWaitEvent(0, evJoin, 0);

    // pull-aggregate with deferred dinv[src] scaling
    gather128_kernel<<<gblk, 256>>>(p_h1s, p_dinv, p_agg1, M);

    // layer 2 GEMM with fused relu(agg1*dinv+b1), epilogue dinv scale
    mma_gcn_kernel<64, true, true><<<nblk, 256, smem2>>>(
        p_agg1, p_Wt2, p_dinv, b1, p_h2s, M);

    // pull-aggregate + fused bias -> out (fp32)
    gather64_out_kernel<<<gblk, 256>>>(p_h2s, p_dinv, b2, out, M);
}